// round 16
// baseline (speedup 1.0000x reference)
#include <cuda_runtime.h>
#include <cuda_bf16.h>
#include <cstdint>
#include <math.h>

// Problem constants (fixed by reference)
#define BB 256
#define PP 16
#define LL 4
#define EE 128
#define NPAIR 4096
#define NNODE 512
#define C1 512
#define C2 256
#define LIST_CAP 64
#define XSTRH 136            // X row stride in bf16 units (272B) -> conflict-free B frags
#define PGRID 296            // persistent blocks: exactly 2 per SM x 148 -> co-resident

typedef unsigned long long ull;
typedef unsigned short ushort_t;

// ---------------- device scratch (no allocations allowed) ----------------
__device__ float g_bufA[NPAIR * 2 * EE];   // 4 MB ping
__device__ float g_bufB[NPAIR * 2 * EE];   // 4 MB pong
__device__ float g_pooledT[2 * EE * BB];
__device__ float g_h1T[C1 * BB];
__device__ float g_h2T[C2 * BB];
__device__ int   g_meta[LL * NNODE];
__device__ int   g_sync[8];
__device__ int   g_list[LL * NNODE * LIST_CAP];

// ---------------- helpers ----------------
__device__ __forceinline__ void fma2(ull& d, ull a, ull b) {
    asm("fma.rn.f32x2 %0, %1, %2, %0;" : "+l"(d) : "l"(a), "l"(b));
}
__device__ __forceinline__ ull pack2(float x) {
    ull r; unsigned u = __float_as_uint(x);
    asm("mov.b64 %0, {%1, %2};" : "=l"(r) : "r"(u), "r"(u));
    return r;
}
__device__ __forceinline__ ull packab(float a, float b) {
    ull r;
    asm("mov.b64 %0, {%1, %2};" : "=l"(r) : "r"(__float_as_uint(a)), "r"(__float_as_uint(b)));
    return r;
}
__device__ __forceinline__ uint32_t cvt_bf16x2(float x0, float x1) {
    uint32_t r;
    asm("cvt.rn.bf16x2.f32 %0, %1, %2;" : "=r"(r) : "f"(x1), "f"(x0));
    return r;
}
__device__ __forceinline__ void split2(float x0, float x1, uint32_t& hi, uint32_t& lo) {
    hi = cvt_bf16x2(x0, x1);
    float h0 = __uint_as_float(hi << 16);
    float h1 = __uint_as_float(hi & 0xffff0000u);
    lo = cvt_bf16x2(x0 - h0, x1 - h1);
}
__device__ __forceinline__ void mma16816(float* c, uint32_t a0, uint32_t a1, uint32_t a2, uint32_t a3,
                                         uint32_t b0, uint32_t b1) {
    asm volatile(
        "mma.sync.aligned.m16n8k16.row.col.f32.bf16.bf16.f32 "
        "{%0,%1,%2,%3}, {%4,%5,%6,%7}, {%8,%9}, {%0,%1,%2,%3};"
        : "+f"(c[0]), "+f"(c[1]), "+f"(c[2]), "+f"(c[3])
        : "r"(a0), "r"(a1), "r"(a2), "r"(a3), "r"(b0), "r"(b1));
}
// grid-wide barrier: all PGRID blocks are co-resident (2/SM by launch_bounds)
__device__ __forceinline__ void gsync(int idx) {
    __syncthreads();
    if (threadIdx.x == 0) {
        volatile int* c = &g_sync[idx];
        __threadfence();                       // release prior writes
        atomicAdd((int*)c, 1);
        while (*c < PGRID) __nanosleep(64);
        __threadfence();                       // acquire others' writes
    }
    __syncthreads();
}

// ---------------- layer phase (device): items = (node, 16-pair chunk slot) ----------------
// 256 threads = 8 warps; warp w computes rows [w*16, w*16+16) x active vectors.
// W fp32 fragment loads, in-register bf16 hi/lo split; 3-product mma.
template <bool FIRST>
__device__ __forceinline__ void layer_phase(
    int layer, const float* __restrict__ Wg, const float* __restrict__ bias,
    const int* __restrict__ sids, const int* __restrict__ eids,
    const float* __restrict__ embed,
    const float* __restrict__ bufIn, float* __restrict__ bufOut,
    ushort_t* sxh, ushort_t* sxl)
{
    const int tid = threadIdx.x, lane = tid & 31, w = tid >> 5;
    const int kbase = (lane & 3) << 1;
    const int brow = lane >> 2;

    for (int slot = blockIdx.x; slot < NNODE * 4; slot += PGRID) {
        const int node = slot >> 2;
        const int c0   = (slot & 3) << 4;
        int kp = g_meta[layer * NNODE + node];
        kp = kp < LIST_CAP ? kp : LIST_CAP;
        if (c0 >= kp) continue;                 // uniform per block
        const int nv = 2 * min(16, kp - c0);
        const int* lst = &g_list[(layer * NNODE + node) * LIST_CAP + c0];

        __syncthreads();                        // prev slot's compute done before overwrite

        // ---- gather X, split into bf16 hi/lo tiles ----
        for (int f = tid; f < nv * 32; f += 256) {
            int v = f >> 5, i4 = f & 31;
            int pr = lst[v >> 1];
            const float4* src;
            if (FIRST) {
                int id = (v & 1) ? eids[pr] : sids[pr];
                src = (const float4*)(embed + (size_t)id * EE);
            } else {
                src = (const float4*)(bufIn + ((size_t)pr * 2 + (v & 1)) * EE);
            }
            float4 x = src[i4];
            uint32_t h01, l01, h23, l23;
            split2(x.x, x.y, h01, l01);
            split2(x.z, x.w, h23, l23);
            int o = v * XSTRH + i4 * 4;
            *(uint2*)&sxh[o] = make_uint2(h01, h23);
            *(uint2*)&sxl[o] = make_uint2(l01, l23);
        }
        __syncthreads();

        // ---- 3-product bf16-split mma with nt-group skipping ----
        float c[4][4];
        #pragma unroll
        for (int nt = 0; nt < 4; ++nt)
            #pragma unroll
            for (int q = 0; q < 4; ++q) c[nt][q] = 0.f;

        const int rbase = w * 16 + (lane >> 2);
        const float* wrow = Wg + (size_t)node * EE * EE + (size_t)rbase * EE + kbase;

        #pragma unroll 2
        for (int s = 0; s < 8; ++s) {
            const float* wp = wrow + s * 16;
            float2 w00 = *(const float2*)wp;
            float2 w10 = *(const float2*)(wp + 8 * EE);
            float2 w01 = *(const float2*)(wp + 8);
            float2 w11 = *(const float2*)(wp + 8 * EE + 8);
            uint32_t ahi[4], alo[4];
            split2(w00.x, w00.y, ahi[0], alo[0]);
            split2(w10.x, w10.y, ahi[1], alo[1]);
            split2(w01.x, w01.y, ahi[2], alo[2]);
            split2(w11.x, w11.y, ahi[3], alo[3]);
            #pragma unroll
            for (int nt = 0; nt < 4; ++nt) {
                if (nt * 8 >= nv) break;        // skip inactive vector groups
                const int xo = (nt * 8 + brow) * XSTRH + s * 16 + kbase;
                uint32_t bh0 = *(const uint32_t*)&sxh[xo];
                uint32_t bh1 = *(const uint32_t*)&sxh[xo + 8];
                uint32_t bl0 = *(const uint32_t*)&sxl[xo];
                uint32_t bl1 = *(const uint32_t*)&sxl[xo + 8];
                mma16816(c[nt], ahi[0], ahi[1], ahi[2], ahi[3], bh0, bh1);
                mma16816(c[nt], ahi[0], ahi[1], ahi[2], ahi[3], bl0, bl1);
                mma16816(c[nt], alo[0], alo[1], alo[2], alo[3], bh0, bh1);
            }
        }

        // ---- epilogue: +bias, guarded scatter ----
        const int r0 = rbase;
        const float bv0 = bias[node * EE + r0];
        const float bv1 = bias[node * EE + r0 + 8];
        #pragma unroll
        for (int nt = 0; nt < 4; ++nt) {
            int v0 = nt * 8 + ((lane & 3) << 1);
            int v1 = v0 + 1;
            if (v0 < nv) {
                int pr = lst[v0 >> 1];
                float* dst = bufOut + ((size_t)pr * 2 + (v0 & 1)) * EE;
                dst[r0]     = c[nt][0] + bv0;
                dst[r0 + 8] = c[nt][2] + bv1;
            }
            if (v1 < nv) {
                int pr = lst[v1 >> 1];
                float* dst = bufOut + ((size_t)pr * 2 + (v1 & 1)) * EE;
                dst[r0]     = c[nt][1] + bv0;
                dst[r0 + 8] = c[nt][3] + bv1;
            }
        }
    }
}

// ---------------- single persistent kernel: build + 4 layers + pool + MLPs + out ----------------
__global__ __launch_bounds__(256, 2) void fused_kernel(
    const int* __restrict__ sids, const int* __restrict__ eids,
    const int* __restrict__ mids, const int* __restrict__ counts,
    const float* __restrict__ embed, const float* __restrict__ Wg,
    const float* __restrict__ bias,
    const float* __restrict__ W1, const float* __restrict__ b1,
    const float* __restrict__ W2, const float* __restrict__ b2,
    const float* __restrict__ W3, const float* __restrict__ b3,
    float* __restrict__ out)
{
    __shared__ ushort_t sxh[32 * XSTRH];
    __shared__ ushort_t sxl[32 * XSTRH];
    __shared__ float wt[C1 * 8];               // MLP weight tile (16 KB)

    const int tid = threadIdx.x, blk = blockIdx.x;

    // ---- phase 0: build (layer,node)->pair lists ----
    {
        int idx = blk * 256 + tid;
        if (idx < NPAIR * LL) {
            int p = idx >> 2, l = idx & 3;
            int node = mids[p * LL + l];
            int pos = atomicAdd(&g_meta[l * NNODE + node], 1);
            if (pos < LIST_CAP)
                g_list[(l * NNODE + node) * LIST_CAP + pos] = p;
        }
    }
    gsync(0);

    // ---- phases 1-4: the layer chain (W stays L2-resident within one kernel) ----
    layer_phase<true >(0, Wg, bias, sids, eids, embed, nullptr, g_bufA, sxh, sxl);
    gsync(1);
    layer_phase<false>(1, Wg, bias, sids, eids, embed, g_bufA, g_bufB, sxh, sxl);
    gsync(2);
    layer_phase<false>(2, Wg, bias, sids, eids, embed, g_bufB, g_bufA, sxh, sxl);
    gsync(3);
    layer_phase<false>(3, Wg, bias, sids, eids, embed, g_bufA, g_bufB, sxh, sxl);
    gsync(4);

    // ---- phase 5: pool -> pooledT[f][b] ----
    if (blk < BB) {
        const int b = blk;
        const int half = tid >> 7, fi = tid & 127;
        float acc = 0.f, cs = 0.f;
        #pragma unroll
        for (int p = 0; p < PP; ++p) {
            float cc = (float)counts[b * PP + p];
            acc += cc * g_bufB[((size_t)((b * PP + p) * 2 + half)) * EE + fi];
            cs += cc;
        }
        g_pooledT[(size_t)tid * BB + b] = acc / cs;
    }
    gsync(5);

    // ---- phase 6: MLP1 (256 -> 512, relu) ----
    if (blk < 256) {
        const int jt = (blk >> 2) * 8;
        const int tb = (blk & 3) * 64;
        for (int f = tid; f < 256 * 8; f += 256) {
            int i = f >> 3, jj = f & 7;
            wt[f] = W1[(size_t)(jt + jj) * 256 + i];
        }
        __syncthreads();
        const int jj = tid >> 5, tt = tid & 31;
        ull acc = 0ull;
        #pragma unroll 8
        for (int i = 0; i < 256; ++i) {
            float x0 = g_pooledT[(size_t)i * BB + tb + tt];
            float x1 = g_pooledT[(size_t)i * BB + tb + tt + 32];
            fma2(acc, pack2(wt[i * 8 + jj]), packab(x0, x1));
        }
        float bv = b1[jt + jj];
        g_h1T[(size_t)(jt + jj) * BB + tb + tt]      = fmaxf(__uint_as_float((unsigned)acc) + bv, 0.f);
        g_h1T[(size_t)(jt + jj) * BB + tb + tt + 32] = fmaxf(__uint_as_float((unsigned)(acc >> 32)) + bv, 0.f);
    }
    gsync(6);

    // ---- phase 7: MLP2 (512 -> 256, relu) ----
    if (blk < 128) {
        const int jt = (blk >> 2) * 8;
        const int tb = (blk & 3) * 64;
        for (int f = tid; f < 512 * 8; f += 256) {
            int i = f >> 3, jj = f & 7;
            wt[f] = W2[(size_t)(jt + jj) * 512 + i];
        }
        __syncthreads();
        const int jj = tid >> 5, tt = tid & 31;
        ull acc = 0ull;
        #pragma unroll 8
        for (int i = 0; i < 512; ++i) {
            float x0 = g_h1T[(size_t)i * BB + tb + tt];
            float x1 = g_h1T[(size_t)i * BB + tb + tt + 32];
            fma2(acc, pack2(wt[i * 8 + jj]), packab(x0, x1));
        }
        float bv = b2[jt + jj];
        g_h2T[(size_t)(jt + jj) * BB + tb + tt]      = fmaxf(__uint_as_float((unsigned)acc) + bv, 0.f);
        g_h2T[(size_t)(jt + jj) * BB + tb + tt + 32] = fmaxf(__uint_as_float((unsigned)(acc >> 32)) + bv, 0.f);
    }
    gsync(7);

    // ---- phase 8: output (block 0) ----
    if (blk == 0) {
        float acc = 0.f;
        #pragma unroll 8
        for (int j = 0; j < C2; ++j)
            acc += W3[j] * g_h2T[(size_t)j * BB + tid];
        acc += b3[0];
        out[tid] = 1.f / (1.f + expf(-acc));
    }
}

// ---------------- launch ----------------
extern "C" void kernel_launch(void* const* d_in, const int* in_sizes, int n_in,
                              void* d_out, int out_size)
{
    const int*   sids   = (const int*)d_in[0];
    const int*   eids   = (const int*)d_in[1];
    const int*   mids   = (const int*)d_in[2];
    const int*   counts = (const int*)d_in[3];
    const float* embed  = (const float*)d_in[4];
    const float* W      = (const float*)d_in[5];
    const float* bnode  = (const float*)d_in[6];
    const float* W1     = (const float*)d_in[7];
    const float* b1     = (const float*)d_in[8];
    const float* W2     = (const float*)d_in[9];
    const float* b2     = (const float*)d_in[10];
    const float* W3     = (const float*)d_in[11];
    const float* b3     = (const float*)d_in[12];

    int *meta, *sync;
    cudaGetSymbolAddress((void**)&meta, g_meta);
    cudaGetSymbolAddress((void**)&sync, g_sync);

    // zero list counters + grid-sync counters every call (deterministic per replay)
    cudaMemsetAsync(meta, 0, LL * NNODE * sizeof(int));
    cudaMemsetAsync(sync, 0, 8 * sizeof(int));

    fused_kernel<<<PGRID, 256>>>(sids, eids, mids, counts, embed, W, bnode,
                                 W1, b1, W2, b2, W3, b3, (float*)d_out);
}

// round 17
// speedup vs baseline: 1.6474x; 1.6474x over previous
#include <cuda_runtime.h>
#include <cuda_bf16.h>
#include <cstdint>
#include <math.h>

// Problem constants (fixed by reference)
#define BB 256
#define PP 16
#define LL 4
#define EE 128
#define NPAIR 4096
#define NNODE 512
#define C1 512
#define C2 256
#define LIST_CAP 64
#define XSTRH 136            // X row stride in bf16 units (272B) -> conflict-free B frags
#define PGRID 888            // persistent blocks: 6/SM x 148 (guaranteed by launch_bounds)
#define NSLOT (NNODE * 4 * 2) // (node, 16-pair chunk, rowhalf)

typedef unsigned long long ull;
typedef unsigned short ushort_t;

// ---------------- device scratch (no allocations allowed) ----------------
__device__ float g_bufA[NPAIR * 2 * EE];   // 4 MB ping
__device__ float g_bufB[NPAIR * 2 * EE];   // 4 MB pong
__device__ float g_pooledT[2 * EE * BB];   // [f][b]
__device__ float g_h1T[C1 * BB];           // [j][b]
__device__ float g_h2T[C2 * BB];           // [j][b]
__device__ int   g_meta[LL * NNODE + 32];  // list counts + barrier counters + tickets
__device__ int   g_list[LL * NNODE * LIST_CAP];

// meta layout: [0, LL*NNODE): per-(layer,node) counts
//   [LL*NNODE + 0..7]  : barrier counters (8 gsyncs)
//   [LL*NNODE + 8..11] : per-layer work-steal tickets
#define SYNC_BASE (LL * NNODE)
#define TICK_BASE (LL * NNODE + 8)

// ---------------- helpers ----------------
__device__ __forceinline__ uint32_t cvt_bf16x2(float x0, float x1) {
    uint32_t r;
    asm("cvt.rn.bf16x2.f32 %0, %1, %2;" : "=r"(r) : "f"(x1), "f"(x0));
    return r;
}
__device__ __forceinline__ void split2(float x0, float x1, uint32_t& hi, uint32_t& lo) {
    hi = cvt_bf16x2(x0, x1);
    float h0 = __uint_as_float(hi << 16);
    float h1 = __uint_as_float(hi & 0xffff0000u);
    lo = cvt_bf16x2(x0 - h0, x1 - h1);
}
__device__ __forceinline__ void mma16816(float* c, uint32_t a0, uint32_t a1, uint32_t a2, uint32_t a3,
                                         uint32_t b0, uint32_t b1) {
    asm volatile(
        "mma.sync.aligned.m16n8k16.row.col.f32.bf16.bf16.f32 "
        "{%0,%1,%2,%3}, {%4,%5,%6,%7}, {%8,%9}, {%0,%1,%2,%3};"
        : "+f"(c[0]), "+f"(c[1]), "+f"(c[2]), "+f"(c[3])
        : "r"(a0), "r"(a1), "r"(a2), "r"(a3), "r"(b0), "r"(b1));
}
// grid-wide barrier: all PGRID blocks co-resident (6/SM via launch_bounds + smem budget)
__device__ __forceinline__ void gsync(int idx) {
    __syncthreads();
    if (threadIdx.x == 0) {
        volatile int* c = (volatile int*)&g_meta[SYNC_BASE + idx];
        __threadfence();
        atomicAdd((int*)c, 1);
        while (*c < PGRID) __nanosleep(64);
        __threadfence();
    }
    __syncthreads();
}

// ---------------- layer phase: work-stealing over (node, chunk, rowhalf) slots ----------------
// 128 threads = 4 warps; warp w computes rows rh*64 + [w*16, w*16+16) x active vectors.
template <bool FIRST>
__device__ __forceinline__ void layer_phase(
    int layer, const float* __restrict__ Wg, const float* __restrict__ bias,
    const int* __restrict__ sids, const int* __restrict__ eids,
    const float* __restrict__ embed,
    const float* __restrict__ bufIn, float* __restrict__ bufOut,
    ushort_t* sxh, ushort_t* sxl, int* s_slot)
{
    const int tid = threadIdx.x, lane = tid & 31, w = tid >> 5;
    const int kbase = (lane & 3) << 1;
    const int brow = lane >> 2;
    int* ticket = &g_meta[TICK_BASE + layer];

    for (;;) {
        if (tid == 0) *s_slot = atomicAdd(ticket, 1);
        __syncthreads();                        // broadcast + guard xs reuse
        const int slot = *s_slot;
        if (slot >= NSLOT) break;

        const int node = slot >> 3;
        const int c0   = ((slot >> 1) & 3) << 4;
        const int rh   = slot & 1;
        int kp = g_meta[layer * NNODE + node];
        kp = kp < LIST_CAP ? kp : LIST_CAP;
        if (c0 >= kp) continue;
        const int nv = 2 * min(16, kp - c0);
        const int* lst = &g_list[(layer * NNODE + node) * LIST_CAP + c0];

        // ---- gather X, split into bf16 hi/lo tiles ----
        for (int f = tid; f < nv * 32; f += 128) {
            int v = f >> 5, i4 = f & 31;
            int pr = lst[v >> 1];
            const float4* src;
            if (FIRST) {
                int id = (v & 1) ? eids[pr] : sids[pr];
                src = (const float4*)(embed + (size_t)id * EE);
            } else {
                src = (const float4*)(bufIn + ((size_t)pr * 2 + (v & 1)) * EE);
            }
            float4 x = src[i4];
            uint32_t h01, l01, h23, l23;
            split2(x.x, x.y, h01, l01);
            split2(x.z, x.w, h23, l23);
            int o = v * XSTRH + i4 * 4;
            *(uint2*)&sxh[o] = make_uint2(h01, h23);
            *(uint2*)&sxl[o] = make_uint2(l01, l23);
        }
        __syncthreads();

        // ---- 3-product bf16-split mma with nt-group skipping ----
        float c[4][4];
        #pragma unroll
        for (int nt = 0; nt < 4; ++nt)
            #pragma unroll
            for (int q = 0; q < 4; ++q) c[nt][q] = 0.f;

        const int rbase = rh * 64 + w * 16 + (lane >> 2);
        const float* wrow = Wg + (size_t)node * EE * EE + (size_t)rbase * EE + kbase;

        #pragma unroll 2
        for (int s = 0; s < 8; ++s) {
            const float* wp = wrow + s * 16;
            float2 w00 = *(const float2*)wp;
            float2 w10 = *(const float2*)(wp + 8 * EE);
            float2 w01 = *(const float2*)(wp + 8);
            float2 w11 = *(const float2*)(wp + 8 * EE + 8);
            uint32_t ahi[4], alo[4];
            split2(w00.x, w00.y, ahi[0], alo[0]);
            split2(w10.x, w10.y, ahi[1], alo[1]);
            split2(w01.x, w01.y, ahi[2], alo[2]);
            split2(w11.x, w11.y, ahi[3], alo[3]);
            #pragma unroll
            for (int nt = 0; nt < 4; ++nt) {
                if (nt * 8 >= nv) break;
                const int xo = (nt * 8 + brow) * XSTRH + s * 16 + kbase;
                uint32_t bh0 = *(const uint32_t*)&sxh[xo];
                uint32_t bh1 = *(const uint32_t*)&sxh[xo + 8];
                uint32_t bl0 = *(const uint32_t*)&sxl[xo];
                uint32_t bl1 = *(const uint32_t*)&sxl[xo + 8];
                mma16816(c[nt], ahi[0], ahi[1], ahi[2], ahi[3], bh0, bh1);
                mma16816(c[nt], ahi[0], ahi[1], ahi[2], ahi[3], bl0, bl1);
                mma16816(c[nt], alo[0], alo[1], alo[2], alo[3], bh0, bh1);
            }
        }

        // ---- epilogue: +bias, guarded scatter ----
        const float bv0 = bias[node * EE + rbase];
        const float bv1 = bias[node * EE + rbase + 8];
        #pragma unroll
        for (int nt = 0; nt < 4; ++nt) {
            int v0 = nt * 8 + ((lane & 3) << 1);
            int v1 = v0 + 1;
            if (v0 < nv) {
                int pr = lst[v0 >> 1];
                float* dst = bufOut + ((size_t)pr * 2 + (v0 & 1)) * EE;
                dst[rbase]     = c[nt][0] + bv0;
                dst[rbase + 8] = c[nt][2] + bv1;
            }
            if (v1 < nv) {
                int pr = lst[v1 >> 1];
                float* dst = bufOut + ((size_t)pr * 2 + (v1 & 1)) * EE;
                dst[rbase]     = c[nt][1] + bv0;
                dst[rbase + 8] = c[nt][3] + bv1;
            }
        }
        __syncthreads();                        // compute done before next gather
    }
}

// ---------------- single persistent kernel ----------------
__global__ __launch_bounds__(128, 6) void fused_kernel(
    const int* __restrict__ sids, const int* __restrict__ eids,
    const int* __restrict__ mids, const int* __restrict__ counts,
    const float* __restrict__ embed, const float* __restrict__ Wg,
    const float* __restrict__ bias,
    const float* __restrict__ W1, const float* __restrict__ b1,
    const float* __restrict__ W2, const float* __restrict__ b2,
    const float* __restrict__ W3, const float* __restrict__ b3,
    float* __restrict__ out)
{
    __shared__ ushort_t sxh[32 * XSTRH];       // 8704 B
    __shared__ ushort_t sxl[32 * XSTRH];       // 8704 B
    __shared__ int s_slot;

    const int tid = threadIdx.x, blk = blockIdx.x;

    // ---- phase 0: build (layer,node)->pair lists (16384 entries over 888x128 threads) ----
    {
        int idx = blk * 128 + tid;
        if (idx < NPAIR * LL) {
            int p = idx >> 2, l = idx & 3;
            int node = mids[p * LL + l];
            int pos = atomicAdd(&g_meta[l * NNODE + node], 1);
            if (pos < LIST_CAP)
                g_list[(l * NNODE + node) * LIST_CAP + pos] = p;
        }
    }
    gsync(0);

    // ---- phases 1-4: layer chain (W read from DRAM once; L2 thereafter) ----
    layer_phase<true >(0, Wg, bias, sids, eids, embed, nullptr, g_bufA, sxh, sxl, &s_slot);
    gsync(1);
    layer_phase<false>(1, Wg, bias, sids, eids, embed, g_bufA, g_bufB, sxh, sxl, &s_slot);
    gsync(2);
    layer_phase<false>(2, Wg, bias, sids, eids, embed, g_bufB, g_bufA, sxh, sxl, &s_slot);
    gsync(3);
    layer_phase<false>(3, Wg, bias, sids, eids, embed, g_bufA, g_bufB, sxh, sxl, &s_slot);
    gsync(4);

    // ---- phase 5: pool — block = batch b (256 blocks); thread covers features t, t+128 ----
    if (blk < BB) {
        const int b = blk;
        float acc0 = 0.f, acc1 = 0.f, cs = 0.f;
        #pragma unroll
        for (int p = 0; p < PP; ++p) {
            float cc = (float)counts[b * PP + p];
            const float* base = g_bufB + (size_t)(b * PP + p) * 2 * EE;
            acc0 += cc * base[tid];            // x half, feature tid
            acc1 += cc * base[EE + tid];       // y half, feature tid
            cs += cc;
        }
        g_pooledT[(size_t)tid * BB + b]        = acc0 / cs;
        g_pooledT[(size_t)(tid + 128) * BB + b] = acc1 / cs;
    }
    gsync(5);

    // ---- phase 6: MLP1 (256 -> 512, relu) — block = output row j (512 blocks) ----
    if (blk < C1) {
        const int j = blk;
        float acc0 = 0.f, acc1 = 0.f;
        const float* w1r = W1 + (size_t)j * 256;
        #pragma unroll 8
        for (int i = 0; i < 256; ++i) {
            float wv = w1r[i];
            acc0 += wv * g_pooledT[(size_t)i * BB + tid];
            acc1 += wv * g_pooledT[(size_t)i * BB + tid + 128];
        }
        float bv = b1[j];
        g_h1T[(size_t)j * BB + tid]       = fmaxf(acc0 + bv, 0.f);
        g_h1T[(size_t)j * BB + tid + 128] = fmaxf(acc1 + bv, 0.f);
    }
    gsync(6);

    // ---- phase 7: MLP2 (512 -> 256, relu) — block = output row j (256 blocks) ----
    if (blk < C2) {
        const int j = blk;
        float acc0 = 0.f, acc1 = 0.f;
        const float* w2r = W2 + (size_t)j * 512;
        #pragma unroll 8
        for (int i = 0; i < 512; ++i) {
            float wv = w2r[i];
            acc0 += wv * g_h1T[(size_t)i * BB + tid];
            acc1 += wv * g_h1T[(size_t)i * BB + tid + 128];
        }
        float bv = b2[j];
        g_h2T[(size_t)j * BB + tid]       = fmaxf(acc0 + bv, 0.f);
        g_h2T[(size_t)j * BB + tid + 128] = fmaxf(acc1 + bv, 0.f);
    }
    gsync(7);

    // ---- phase 8: output — blocks 0,1 cover 256 batches ----
    if (blk < 2) {
        const int t = blk * 128 + tid;
        float acc = 0.f;
        #pragma unroll 8
        for (int j = 0; j < C2; ++j)
            acc += W3[j] * g_h2T[(size_t)j * BB + t];
        acc += b3[0];
        out[t] = 1.f / (1.f + expf(-acc));
    }
}

// ---------------- launch ----------------
extern "C" void kernel_launch(void* const* d_in, const int* in_sizes, int n_in,
                              void* d_out, int out_size)
{
    const int*   sids   = (const int*)d_in[0];
    const int*   eids   = (const int*)d_in[1];
    const int*   mids   = (const int*)d_in[2];
    const int*   counts = (const int*)d_in[3];
    const float* embed  = (const float*)d_in[4];
    const float* W      = (const float*)d_in[5];
    const float* bnode  = (const float*)d_in[6];
    const float* W1     = (const float*)d_in[7];
    const float* b1     = (const float*)d_in[8];
    const float* W2     = (const float*)d_in[9];
    const float* b2     = (const float*)d_in[10];
    const float* W3     = (const float*)d_in[11];
    const float* b3     = (const float*)d_in[12];

    int* meta;
    cudaGetSymbolAddress((void**)&meta, g_meta);

    // zero list counts + barrier counters + tickets (deterministic per replay)
    cudaMemsetAsync(meta, 0, (LL * NNODE + 32) * sizeof(int));

    fused_kernel<<<PGRID, 128>>>(sids, eids, mids, counts, embed, W, bnode,
                                 W1, b1, W2, b2, W3, b3, (float*)d_out);
}